// round 2
// baseline (speedup 1.0000x reference)
#include <cuda_runtime.h>

#define NN 100000
#define EE 1200000
#define HID 64
#define NG 256
#define OC 10

// ---- scratch (static device globals; no allocation allowed) ----
__device__ float g_deg[NN];
__device__ float g_dis[NN];
__device__ float g_hw[NN * HID];
__device__ float g_agg[NN * HID];
__device__ float g_sums[NG * HID];
__device__ float g_cnt[NG];

// ---- init: deg=1 (self loop), pool accumulators = 0 ----
__global__ void k_init() {
    int i = blockIdx.x * blockDim.x + threadIdx.x;
    if (i < NN) g_deg[i] = 1.0f;
    if (i < NG * HID) g_sums[i] = 0.0f;
    if (i < NG) g_cnt[i] = 0.0f;
}

// ---- degree: deg[dst] += 1 over edges (indices are int32) ----
__global__ void k_deg(const int* __restrict__ ei) {
    int e = blockIdx.x * blockDim.x + threadIdx.x;
    if (e < EE) atomicAdd(&g_deg[ei[EE + e]], 1.0f);
}

__global__ void k_dis() {
    int i = blockIdx.x * blockDim.x + threadIdx.x;
    if (i < NN) g_dis[i] = rsqrtf(g_deg[i]);
}

// ---- fused dense: hw = (relu?)(h) @ W ; agg = dis^2*hw + b  ----
// 256 threads = 4 nodes x 64 channels per block.
// FROM_AGG: read input from g_agg instead of the h pointer.
template <int IN, bool RELU_IN, bool FROM_AGG>
__global__ void k_mm(const float* __restrict__ h,
                     const float* __restrict__ W,
                     const float* __restrict__ b) {
    __shared__ float Ws[IN * HID];
    __shared__ float hs[4 * IN];
    int t = threadIdx.x;
    for (int i = t; i < IN * HID; i += 256) Ws[i] = W[i];
    int node0 = blockIdx.x * 4;
    const float* __restrict__ src = FROM_AGG ? g_agg : h;
    for (int i = t; i < 4 * IN; i += 256) {
        int nd = node0 + i / IN;
        float v = (nd < NN) ? src[(long long)nd * IN + (i % IN)] : 0.0f;
        if (RELU_IN) v = fmaxf(v, 0.0f);
        hs[i] = v;
    }
    __syncthreads();
    int node = node0 + t / HID;
    int c = t % HID;
    if (node < NN) {
        const float* hrow = &hs[(t / HID) * IN];
        float s = 0.0f;
#pragma unroll
        for (int k = 0; k < IN; k++) s += hrow[k] * Ws[k * HID + c];
        float d = g_dis[node];
        g_hw[node * HID + c] = s;
        g_agg[node * HID + c] = d * d * s + b[c];
    }
}

// ---- edge scatter: agg[dst] += dis[src]*dis[dst] * hw[src]  (warp/edge) ----
__global__ void k_scatter(const int* __restrict__ ei) {
    int w = (blockIdx.x * blockDim.x + threadIdx.x) >> 5;
    int lane = threadIdx.x & 31;
    if (w >= EE) return;
    int src = ei[w];
    int dst = ei[EE + w];
    float nrm = g_dis[src] * g_dis[dst];
    const float* __restrict__ hp = &g_hw[src * HID];
    float* __restrict__ ap = &g_agg[dst * HID];
    atomicAdd(&ap[lane], nrm * hp[lane]);
    atomicAdd(&ap[lane + 32], nrm * hp[lane + 32]);
}

// ---- global mean pool (sums + counts) ----
__global__ void k_pool(const int* __restrict__ batch) {
    long long idx = (long long)blockIdx.x * blockDim.x + threadIdx.x;
    if (idx >= (long long)NN * HID) return;
    int node = (int)(idx / HID);
    int c = (int)(idx % HID);
    int g = batch[node];
    atomicAdd(&g_sums[g * HID + c], g_agg[idx]);
    if (c == 0) atomicAdd(&g_cnt[g], 1.0f);
}

// ---- final: out = (sums/cnt) @ lin_W + lin_b  (1 block, 256 graphs) ----
__global__ void k_fin(const float* __restrict__ lw,
                      const float* __restrict__ lb,
                      float* __restrict__ out) {
    int g = threadIdx.x;
    if (g >= NG) return;
    float inv = 1.0f / fmaxf(g_cnt[g], 1.0f);
    float acc[OC];
#pragma unroll
    for (int o = 0; o < OC; o++) acc[o] = lb[o];
    for (int k = 0; k < HID; k++) {
        float v = g_sums[g * HID + k] * inv;
#pragma unroll
        for (int o = 0; o < OC; o++) acc[o] += v * lw[k * OC + o];
    }
#pragma unroll
    for (int o = 0; o < OC; o++) out[g * OC + o] = acc[o];
}

extern "C" void kernel_launch(void* const* d_in, const int* in_sizes, int n_in,
                              void* d_out, int out_size) {
    const float* x   = (const float*)d_in[0];
    const int* ei    = (const int*)d_in[1];   // int32 indices per harness contract
    const int* bat   = (const int*)d_in[2];
    const float* W0  = (const float*)d_in[3];
    const float* b0  = (const float*)d_in[4];
    const float* W1  = (const float*)d_in[5];
    const float* b1  = (const float*)d_in[6];
    const float* W2  = (const float*)d_in[7];
    const float* b2  = (const float*)d_in[8];
    const float* lw  = (const float*)d_in[9];
    const float* lb  = (const float*)d_in[10];
    float* out       = (float*)d_out;

    const int TB = 256;
    k_init<<<(NN + TB - 1) / TB, TB>>>();
    k_deg<<<(EE + TB - 1) / TB, TB>>>(ei);
    k_dis<<<(NN + TB - 1) / TB, TB>>>();

    int mm_grid = (NN + 3) / 4;
    int sc_grid = (int)(((long long)EE * 32 + TB - 1) / TB);

    // layer 0: input x [N,7]
    k_mm<7, false, false><<<mm_grid, TB>>>(x, W0, b0);
    k_scatter<<<sc_grid, TB>>>(ei);
    // layer 1: input relu(agg)
    k_mm<64, true, true><<<mm_grid, TB>>>(nullptr, W1, b1);
    k_scatter<<<sc_grid, TB>>>(ei);
    // layer 2: input relu(agg), output no relu
    k_mm<64, true, true><<<mm_grid, TB>>>(nullptr, W2, b2);
    k_scatter<<<sc_grid, TB>>>(ei);

    long long pool_threads = (long long)NN * HID;
    k_pool<<<(int)((pool_threads + TB - 1) / TB), TB>>>(bat);
    k_fin<<<1, TB>>>(lw, lb, out);
}

// round 3
// speedup vs baseline: 1.0119x; 1.0119x over previous
#include <cuda_runtime.h>

#define NN 100000
#define EE 1200000
#define HID 64
#define NG 256
#define OC 10

// ---- scratch (static device globals; no allocation allowed) ----
__device__ float g_deg[NN];
__device__ float g_dis[NN];
__device__ float g_hw[NN * HID];
__device__ float g_agg[NN * HID];
__device__ float g_sums[NG * HID];
__device__ float g_cnt[NG];

// ---- init: deg=1 (self loop), pool accumulators = 0 ----
__global__ void k_init() {
    int i = blockIdx.x * blockDim.x + threadIdx.x;
    if (i < NN) g_deg[i] = 1.0f;
    if (i < NG * HID) g_sums[i] = 0.0f;
    if (i < NG) g_cnt[i] = 0.0f;
}

// ---- degree: deg[dst] += 1 over edges (indices are int32) ----
__global__ void k_deg(const int* __restrict__ ei) {
    int e = blockIdx.x * blockDim.x + threadIdx.x;
    if (e < EE) atomicAdd(&g_deg[ei[EE + e]], 1.0f);
}

__global__ void k_dis() {
    int i = blockIdx.x * blockDim.x + threadIdx.x;
    if (i < NN) g_dis[i] = rsqrtf(g_deg[i]);
}

// ---- fused dense: hw = (relu?)(h) @ W ; agg = dis^2*hw + b ----
// 256 threads, 16 nodes/block; each thread emits a float4 of channels.
template <int IN, bool RELU_IN, bool FROM_AGG>
__global__ void k_mm(const float* __restrict__ h,
                     const float* __restrict__ W,
                     const float* __restrict__ b) {
    __shared__ float4 Ws[IN * 16];   // W[k][c] as 16 float4s per k
    __shared__ float  hs[16 * IN];
    __shared__ float4 bs[16];
    int t = threadIdx.x;
    for (int i = t; i < IN * 16; i += 256) Ws[i] = ((const float4*)W)[i];
    if (t < 16) bs[t] = ((const float4*)b)[t];
    int node0 = blockIdx.x * 16;
    const float* __restrict__ src = FROM_AGG ? g_agg : h;
    for (int i = t; i < 16 * IN; i += 256) {
        int nd = node0 + i / IN;
        float v = (nd < NN) ? src[(long long)nd * IN + (i % IN)] : 0.0f;
        if (RELU_IN) v = fmaxf(v, 0.0f);
        hs[i] = v;
    }
    __syncthreads();
    int node = node0 + (t >> 4);
    int q = t & 15;
    if (node < NN) {
        const float* hrow = &hs[(t >> 4) * IN];
        float4 s = make_float4(0.f, 0.f, 0.f, 0.f);
#pragma unroll
        for (int k = 0; k < IN; k++) {
            float hv = hrow[k];
            float4 w = Ws[k * 16 + q];
            s.x += hv * w.x; s.y += hv * w.y; s.z += hv * w.z; s.w += hv * w.w;
        }
        float d = g_dis[node];
        float dd = d * d;
        float4 bq = bs[q];
        ((float4*)&g_hw[node * HID])[q] = s;
        float4 a = make_float4(dd * s.x + bq.x, dd * s.y + bq.y,
                               dd * s.z + bq.z, dd * s.w + bq.w);
        ((float4*)&g_agg[node * HID])[q] = a;
    }
}

// ---- edge scatter: agg[dst] += dis[src]*dis[dst] * hw[src] ----
// 16 threads per edge, one float4 RED per thread.
__global__ void k_scatter(const int* __restrict__ ei) {
    long long tid = (long long)blockIdx.x * blockDim.x + threadIdx.x;
    int e = (int)(tid >> 4);
    int q = (int)(tid & 15);
    if (e >= EE) return;
    int src = ei[e];
    int dst = ei[EE + e];
    float nrm = g_dis[src] * g_dis[dst];
    float4 v = ((const float4*)&g_hw[src * HID])[q];
    v.x *= nrm; v.y *= nrm; v.z *= nrm; v.w *= nrm;
    atomicAdd((float4*)&g_agg[dst * HID] + q, v);
}

// ---- global mean pool: batch is sorted -> sequential accumulate + flush ----
// 64 threads/block (thread = channel), NPB nodes per block.
#define NPB 256
__global__ void k_pool(const int* __restrict__ batch) {
    int c = threadIdx.x;          // 0..63
    int n0 = blockIdx.x * NPB;
    int n1 = min(n0 + NPB, NN);
    int cur_g = batch[n0];
    float acc = 0.0f;
    float cnt = 0.0f;
    for (int n = n0; n < n1; n++) {
        int g = batch[n];
        if (g != cur_g) {
            atomicAdd(&g_sums[cur_g * HID + c], acc);
            if (c == 0) atomicAdd(&g_cnt[cur_g], cnt);
            acc = 0.0f; cnt = 0.0f; cur_g = g;
        }
        acc += g_agg[(long long)n * HID + c];
        cnt += 1.0f;
    }
    atomicAdd(&g_sums[cur_g * HID + c], acc);
    if (c == 0) atomicAdd(&g_cnt[cur_g], cnt);
}

// ---- final: out = (sums/cnt) @ lin_W + lin_b  (1 block, 256 graphs) ----
__global__ void k_fin(const float* __restrict__ lw,
                      const float* __restrict__ lb,
                      float* __restrict__ out) {
    int g = threadIdx.x;
    if (g >= NG) return;
    float inv = 1.0f / fmaxf(g_cnt[g], 1.0f);
    float acc[OC];
#pragma unroll
    for (int o = 0; o < OC; o++) acc[o] = lb[o];
    for (int k = 0; k < HID; k++) {
        float v = g_sums[g * HID + k] * inv;
#pragma unroll
        for (int o = 0; o < OC; o++) acc[o] += v * lw[k * OC + o];
    }
#pragma unroll
    for (int o = 0; o < OC; o++) out[g * OC + o] = acc[o];
}

extern "C" void kernel_launch(void* const* d_in, const int* in_sizes, int n_in,
                              void* d_out, int out_size) {
    const float* x   = (const float*)d_in[0];
    const int* ei    = (const int*)d_in[1];
    const int* bat   = (const int*)d_in[2];
    const float* W0  = (const float*)d_in[3];
    const float* b0  = (const float*)d_in[4];
    const float* W1  = (const float*)d_in[5];
    const float* b1  = (const float*)d_in[6];
    const float* W2  = (const float*)d_in[7];
    const float* b2  = (const float*)d_in[8];
    const float* lw  = (const float*)d_in[9];
    const float* lb  = (const float*)d_in[10];
    float* out       = (float*)d_out;

    const int TB = 256;
    k_init<<<(NN + TB - 1) / TB, TB>>>();
    k_deg<<<(EE + TB - 1) / TB, TB>>>(ei);
    k_dis<<<(NN + TB - 1) / TB, TB>>>();

    int mm_grid = (NN + 15) / 16;
    int sc_grid = (int)(((long long)EE * 16 + TB - 1) / TB);

    // layer 0: input x [N,7]
    k_mm<7, false, false><<<mm_grid, TB>>>(x, W0, b0);
    k_scatter<<<sc_grid, TB>>>(ei);
    // layer 1: input relu(agg)
    k_mm<64, true, true><<<mm_grid, TB>>>(nullptr, W1, b1);
    k_scatter<<<sc_grid, TB>>>(ei);
    // layer 2: input relu(agg), output no relu
    k_mm<64, true, true><<<mm_grid, TB>>>(nullptr, W2, b2);
    k_scatter<<<sc_grid, TB>>>(ei);

    k_pool<<<(NN + NPB - 1) / NPB, 64>>>(bat);
    k_fin<<<1, TB>>>(lw, lb, out);
}

// round 4
// speedup vs baseline: 1.8881x; 1.8660x over previous
#include <cuda_runtime.h>

#define NN 100000
#define EE 1200000
#define HID 64
#define NG 256
#define OC 10
#define IN0 7
#define NB ((NN + 255) / 256)   // 391 scan blocks

// ---- scratch (static device globals) ----
__device__ int   g_cnti[NN];        // per-dst edge count (degree w/o self loop)
__device__ int   g_rowp[NN];        // exclusive prefix (CSR row start)
__device__ int   g_cursor[NN];
__device__ int   g_bsum[512];
__device__ int   g_csr[EE];         // src per CSR slot
__device__ float g_wgt[EE];         // dis[src]*dis[dst] per CSR slot
__device__ float g_dis[NN];
__device__ float g_aggx[NN * IN0];  // layer-0 aggregated input
__device__ float g_hw[NN * HID];
__device__ float g_agg[NN * HID];
__device__ float g_sums[NG * HID];
__device__ float g_gcnt[NG];

// ---- zero counters ----
__global__ void k_zero() {
    int i = blockIdx.x * blockDim.x + threadIdx.x;
    if (i < NN) g_cnti[i] = 0;
    if (i < NG * HID) g_sums[i] = 0.0f;
    if (i < NG) g_gcnt[i] = 0.0f;
}

// ---- histogram on dst ----
__global__ void k_hist(const int* __restrict__ ei) {
    int e = blockIdx.x * blockDim.x + threadIdx.x;
    if (e < EE) atomicAdd(&g_cnti[ei[EE + e]], 1);
}

// ---- two-level exclusive scan over g_cnti -> g_rowp ----
__global__ void k_scan1() {
    __shared__ int sm[256];
    int t = threadIdx.x;
    int i = blockIdx.x * 256 + t;
    int v = (i < NN) ? g_cnti[i] : 0;
    sm[t] = v;
    __syncthreads();
#pragma unroll
    for (int off = 1; off < 256; off <<= 1) {
        int add = (t >= off) ? sm[t - off] : 0;
        __syncthreads();
        sm[t] += add;
        __syncthreads();
    }
    if (i < NN) g_rowp[i] = sm[t] - v;          // exclusive
    if (t == 255) g_bsum[blockIdx.x] = sm[255]; // block total
}

__global__ void k_scan2() {
    __shared__ int sm[512];
    int t = threadIdx.x;
    int v = (t < NB) ? g_bsum[t] : 0;
    sm[t] = v;
    __syncthreads();
#pragma unroll
    for (int off = 1; off < 512; off <<= 1) {
        int add = (t >= off) ? sm[t - off] : 0;
        __syncthreads();
        sm[t] += add;
        __syncthreads();
    }
    if (t < NB) g_bsum[t] = sm[t] - v;          // exclusive block offsets
}

__global__ void k_scan3() {
    int i = blockIdx.x * blockDim.x + threadIdx.x;
    if (i >= NN) return;
    int r = g_rowp[i] + g_bsum[i >> 8];
    g_rowp[i] = r;
    g_cursor[i] = r;
    g_dis[i] = rsqrtf((float)g_cnti[i] + 1.0f);
}

// ---- fill CSR: slot per edge under dst, store src + norm weight ----
__global__ void k_fill(const int* __restrict__ ei) {
    int e = blockIdx.x * blockDim.x + threadIdx.x;
    if (e >= EE) return;
    int src = ei[e];
    int dst = ei[EE + e];
    int pos = atomicAdd(&g_cursor[dst], 1);
    g_csr[pos] = src;
    g_wgt[pos] = g_dis[src] * g_dis[dst];
}

// ---- layer-0 gather in input space: aggx[n] = dd*x[n] + sum w*x[src] ----
// 8 threads per node (7 active channels), 32 nodes per 256-thread block.
__global__ void k_gather7(const float* __restrict__ x) {
    int t = threadIdx.x;
    int n = blockIdx.x * 32 + (t >> 3);
    int c = t & 7;
    if (n >= NN || c >= IN0) return;
    int s0 = g_rowp[n], deg = g_cnti[n];
    float d = g_dis[n];
    float acc = d * d * x[(long long)n * IN0 + c];
    for (int e = 0; e < deg; e++) {
        int s = g_csr[s0 + e];
        float w = g_wgt[s0 + e];
        acc += w * x[(long long)s * IN0 + c];
    }
    g_aggx[(long long)n * IN0 + c] = acc;
}

// ---- dense: out = (relu?)(in) @ W (+ b if TO_AGG) ----
// 256 threads, 16 nodes/block; thread emits a float4 of channels.
template <int IN, bool RELU_IN, bool TO_AGG>
__global__ void k_mm(const float* __restrict__ h,
                     const float* __restrict__ W,
                     const float* __restrict__ b) {
    __shared__ float4 Ws[IN * 16];
    __shared__ float  hs[16 * IN];
    __shared__ float4 bs[16];
    int t = threadIdx.x;
    for (int i = t; i < IN * 16; i += 256) Ws[i] = ((const float4*)W)[i];
    if (TO_AGG && t < 16) bs[t] = ((const float4*)b)[t];
    int node0 = blockIdx.x * 16;
    for (int i = t; i < 16 * IN; i += 256) {
        int nd = node0 + i / IN;
        float v = (nd < NN) ? h[(long long)nd * IN + (i % IN)] : 0.0f;
        if (RELU_IN) v = fmaxf(v, 0.0f);
        hs[i] = v;
    }
    __syncthreads();
    int node = node0 + (t >> 4);
    int q = t & 15;
    if (node < NN) {
        const float* hrow = &hs[(t >> 4) * IN];
        float4 s = make_float4(0.f, 0.f, 0.f, 0.f);
#pragma unroll
        for (int k = 0; k < IN; k++) {
            float hv = hrow[k];
            float4 w = Ws[k * 16 + q];
            s.x += hv * w.x; s.y += hv * w.y; s.z += hv * w.z; s.w += hv * w.w;
        }
        if (TO_AGG) {
            float4 bq = bs[q];
            s.x += bq.x; s.y += bq.y; s.z += bq.z; s.w += bq.w;
            ((float4*)&g_agg[(long long)node * HID])[q] = s;
        } else {
            ((float4*)&g_hw[(long long)node * HID])[q] = s;
        }
    }
}

// ---- 64-ch gather: agg[n] = dd*hw[n] + b + sum w*hw[src] ----
// 16 threads per node (float4 quarters), 16 nodes per 256-thread block.
__global__ void k_gather64(const float* __restrict__ b) {
    __shared__ float4 bs[16];
    int t = threadIdx.x;
    if (t < 16) bs[t] = ((const float4*)b)[t];
    __syncthreads();
    int n = blockIdx.x * 16 + (t >> 4);
    int q = t & 15;
    if (n >= NN) return;
    int s0 = g_rowp[n], deg = g_cnti[n];
    float d = g_dis[n];
    float dd = d * d;
    float4 acc = ((const float4*)&g_hw[(long long)n * HID])[q];
    float4 bq = bs[q];
    acc.x = dd * acc.x + bq.x; acc.y = dd * acc.y + bq.y;
    acc.z = dd * acc.z + bq.z; acc.w = dd * acc.w + bq.w;
    for (int e = 0; e < deg; e++) {
        int s = g_csr[s0 + e];
        float w = g_wgt[s0 + e];
        float4 v = ((const float4*)&g_hw[(long long)s * HID])[q];
        acc.x += w * v.x; acc.y += w * v.y; acc.z += w * v.z; acc.w += w * v.w;
    }
    ((float4*)&g_agg[(long long)n * HID])[q] = acc;
}

// ---- global mean pool: batch sorted -> sequential accumulate + flush ----
#define NPB 256
__global__ void k_pool(const int* __restrict__ batch) {
    int c = threadIdx.x;          // 0..63
    int n0 = blockIdx.x * NPB;
    int n1 = min(n0 + NPB, NN);
    int cur_g = batch[n0];
    float acc = 0.0f, cnt = 0.0f;
    for (int n = n0; n < n1; n++) {
        int g = batch[n];
        if (g != cur_g) {
            atomicAdd(&g_sums[cur_g * HID + c], acc);
            if (c == 0) atomicAdd(&g_gcnt[cur_g], cnt);
            acc = 0.0f; cnt = 0.0f; cur_g = g;
        }
        acc += g_agg[(long long)n * HID + c];
        cnt += 1.0f;
    }
    atomicAdd(&g_sums[cur_g * HID + c], acc);
    if (c == 0) atomicAdd(&g_gcnt[cur_g], cnt);
}

// ---- final linear ----
__global__ void k_fin(const float* __restrict__ lw,
                      const float* __restrict__ lb,
                      float* __restrict__ out) {
    int g = threadIdx.x;
    if (g >= NG) return;
    float inv = 1.0f / fmaxf(g_gcnt[g], 1.0f);
    float acc[OC];
#pragma unroll
    for (int o = 0; o < OC; o++) acc[o] = lb[o];
    for (int k = 0; k < HID; k++) {
        float v = g_sums[g * HID + k] * inv;
#pragma unroll
        for (int o = 0; o < OC; o++) acc[o] += v * lw[k * OC + o];
    }
#pragma unroll
    for (int o = 0; o < OC; o++) out[g * OC + o] = acc[o];
}

extern "C" void kernel_launch(void* const* d_in, const int* in_sizes, int n_in,
                              void* d_out, int out_size) {
    const float* x   = (const float*)d_in[0];
    const int* ei    = (const int*)d_in[1];
    const int* bat   = (const int*)d_in[2];
    const float* W0  = (const float*)d_in[3];
    const float* b0  = (const float*)d_in[4];
    const float* W1  = (const float*)d_in[5];
    const float* b1  = (const float*)d_in[6];
    const float* W2  = (const float*)d_in[7];
    const float* b2  = (const float*)d_in[8];
    const float* lw  = (const float*)d_in[9];
    const float* lb  = (const float*)d_in[10];
    float* out       = (float*)d_out;

    const int TB = 256;
    // CSR build
    k_zero<<<(NN + TB - 1) / TB, TB>>>();
    k_hist<<<(EE + TB - 1) / TB, TB>>>(ei);
    k_scan1<<<NB, 256>>>();
    k_scan2<<<1, 512>>>();
    k_scan3<<<(NN + TB - 1) / TB, TB>>>();
    k_fill<<<(EE + TB - 1) / TB, TB>>>(ei);

    int mm_grid = (NN + 15) / 16;
    int g64_grid = (NN + 15) / 16;

    // layer 0: aggregate x (7ch), then mm -> g_agg (+b0)
    k_gather7<<<(NN + 31) / 32, TB>>>(x);
    float* aggx_ptr;  // device-symbol address only used host-side for arg
    cudaGetSymbolAddress((void**)&aggx_ptr, g_aggx);
    k_mm<IN0, false, true><<<mm_grid, TB>>>(aggx_ptr, W0, b0);

    // layer 1: hw = relu(agg)@W1 ; agg = gather(hw)+b1
    float* agg_ptr;
    cudaGetSymbolAddress((void**)&agg_ptr, g_agg);
    k_mm<HID, true, false><<<mm_grid, TB>>>(agg_ptr, W1, nullptr);
    k_gather64<<<g64_grid, TB>>>(b1);

    // layer 2
    k_mm<HID, true, false><<<mm_grid, TB>>>(agg_ptr, W2, nullptr);
    k_gather64<<<g64_grid, TB>>>(b2);

    // pool + linear
    k_pool<<<(NN + NPB - 1) / NPB, 64>>>(bat);
    k_fin<<<1, TB>>>(lw, lb, out);
}

// round 5
// speedup vs baseline: 1.9664x; 1.0414x over previous
#include <cuda_runtime.h>

#define NN 100000
#define EE 1200000
#define HID 64
#define NG 256
#define OC 10
#define IN0 7
#define NB ((NN + 255) / 256)   // 391 scan blocks

// ---- scratch (static device globals) ----
__device__ int   g_cnti[NN];
__device__ int   g_rowp[NN];
__device__ int   g_cursor[NN];
__device__ int   g_bsum[512];
__device__ int   g_csr[EE];
__device__ float g_wgt[EE];
__device__ float g_dis[NN];
__device__ float g_aggx[NN * IN0];
__device__ float g_hw[NN * HID];
__device__ float g_agg[NN * HID];
__device__ float g_sums[NG * HID];
__device__ float g_gcnt[NG];

// ---- zero counters ----
__global__ void k_zero() {
    int i = blockIdx.x * blockDim.x + threadIdx.x;
    if (i < NN) g_cnti[i] = 0;
    if (i < NG * HID) g_sums[i] = 0.0f;
    if (i < NG) g_gcnt[i] = 0.0f;
}

// ---- histogram on dst ----
__global__ void k_hist(const int* __restrict__ ei) {
    int e = blockIdx.x * blockDim.x + threadIdx.x;
    if (e < EE) atomicAdd(&g_cnti[ei[EE + e]], 1);
}

// ---- two-level exclusive scan over g_cnti -> g_rowp ----
__global__ void k_scan1() {
    __shared__ int sm[256];
    int t = threadIdx.x;
    int i = blockIdx.x * 256 + t;
    int v = (i < NN) ? g_cnti[i] : 0;
    sm[t] = v;
    __syncthreads();
#pragma unroll
    for (int off = 1; off < 256; off <<= 1) {
        int add = (t >= off) ? sm[t - off] : 0;
        __syncthreads();
        sm[t] += add;
        __syncthreads();
    }
    if (i < NN) g_rowp[i] = sm[t] - v;
    if (t == 255) g_bsum[blockIdx.x] = sm[255];
}

__global__ void k_scan2() {
    __shared__ int sm[512];
    int t = threadIdx.x;
    int v = (t < NB) ? g_bsum[t] : 0;
    sm[t] = v;
    __syncthreads();
#pragma unroll
    for (int off = 1; off < 512; off <<= 1) {
        int add = (t >= off) ? sm[t - off] : 0;
        __syncthreads();
        sm[t] += add;
        __syncthreads();
    }
    if (t < NB) g_bsum[t] = sm[t] - v;
}

__global__ void k_scan3() {
    int i = blockIdx.x * blockDim.x + threadIdx.x;
    if (i >= NN) return;
    int r = g_rowp[i] + g_bsum[i >> 8];
    g_rowp[i] = r;
    g_cursor[i] = r;
    g_dis[i] = rsqrtf((float)g_cnti[i] + 1.0f);
}

// ---- fill CSR ----
__global__ void k_fill(const int* __restrict__ ei) {
    int e = blockIdx.x * blockDim.x + threadIdx.x;
    if (e >= EE) return;
    int src = ei[e];
    int dst = ei[EE + e];
    int pos = atomicAdd(&g_cursor[dst], 1);
    g_csr[pos] = src;
    g_wgt[pos] = g_dis[src] * g_dis[dst];
}

// ---- layer-0 gather in input space (7ch), 8 threads/node ----
__global__ void k_gather7(const float* __restrict__ x) {
    int t = threadIdx.x;
    int n = blockIdx.x * 32 + (t >> 3);
    int c = t & 7;
    if (n >= NN || c >= IN0) return;
    int s0 = g_rowp[n], deg = g_cnti[n];
    float d = g_dis[n];
    float acc0 = d * d * x[(long long)n * IN0 + c];
    float acc1 = 0.0f;
    int e = s0, end = s0 + deg;
    for (; e + 1 < end; e += 2) {
        int sa = g_csr[e], sb = g_csr[e + 1];
        float wa = g_wgt[e], wb = g_wgt[e + 1];
        acc0 += wa * x[(long long)sa * IN0 + c];
        acc1 += wb * x[(long long)sb * IN0 + c];
    }
    if (e < end) acc0 += g_wgt[e] * x[(long long)g_csr[e] * IN0 + c];
    g_aggx[(long long)n * IN0 + c] = acc0 + acc1;
}

// ---- dense mm7: agg = aggx @ W0 + b0 (per-node map) ----
__global__ void k_mm7(const float* __restrict__ W,
                      const float* __restrict__ b) {
    __shared__ float4 Ws[IN0 * 16];
    __shared__ float  hs[16 * IN0];
    __shared__ float4 bs[16];
    int t = threadIdx.x;
    if (t < IN0 * 16) Ws[t] = ((const float4*)W)[t];
    if (t < 16) bs[t] = ((const float4*)b)[t];
    int node0 = blockIdx.x * 16;
    for (int i = t; i < 16 * IN0; i += 256) {
        int nd = node0 + i / IN0;
        hs[i] = (nd < NN) ? g_aggx[(long long)nd * IN0 + (i % IN0)] : 0.0f;
    }
    __syncthreads();
    int node = node0 + (t >> 4);
    int q = t & 15;
    if (node < NN) {
        const float* hrow = &hs[(t >> 4) * IN0];
        float4 s = bs[q];
#pragma unroll
        for (int k = 0; k < IN0; k++) {
            float hv = hrow[k];
            float4 w = Ws[k * 16 + q];
            s.x += hv * w.x; s.y += hv * w.y; s.z += hv * w.z; s.w += hv * w.w;
        }
        ((float4*)&g_agg[(long long)node * HID])[q] = s;
    }
}

// ---- dense mm64: hw = relu(agg) @ W  (float4-staged) ----
__global__ void k_mm64(const float* __restrict__ W) {
    __shared__ float4 Ws4[HID * 16];    // 16 KB
    __shared__ float4 hs4[16 * 16];     // 4 KB : 16 nodes x 16 float4
    int t = threadIdx.x;
#pragma unroll
    for (int i = 0; i < 4; i++) Ws4[t + 256 * i] = ((const float4*)W)[t + 256 * i];
    int node0 = blockIdx.x * 16;
    int nl = t >> 4;
    int q = t & 15;
    int node = node0 + nl;
    {
        float4 v = make_float4(0.f, 0.f, 0.f, 0.f);
        if (node < NN) v = ((const float4*)&g_agg[(long long)node * HID])[q];
        v.x = fmaxf(v.x, 0.f); v.y = fmaxf(v.y, 0.f);
        v.z = fmaxf(v.z, 0.f); v.w = fmaxf(v.w, 0.f);
        hs4[nl * 16 + q] = v;
    }
    __syncthreads();
    if (node < NN) {
        const float* hrow = (const float*)&hs4[nl * 16];
        float4 s = make_float4(0.f, 0.f, 0.f, 0.f);
#pragma unroll
        for (int k = 0; k < HID; k++) {
            float hv = hrow[k];
            float4 w = Ws4[k * 16 + q];
            s.x += hv * w.x; s.y += hv * w.y; s.z += hv * w.z; s.w += hv * w.w;
        }
        ((float4*)&g_hw[(long long)node * HID])[q] = s;
    }
}

// ---- 64-ch gather, 8 threads/node x 2 float4, 2-edge unroll ----
__global__ void k_gather64(const float* __restrict__ b) {
    int t = threadIdx.x;
    int n = blockIdx.x * 32 + (t >> 3);
    int q = t & 7;                     // quarters q and q+8
    if (n >= NN) return;
    int s0 = g_rowp[n], deg = g_cnti[n];
    float d = g_dis[n];
    float dd = d * d;
    const float4* hp = (const float4*)&g_hw[(long long)n * HID];
    float4 a0 = hp[q], a1 = hp[q + 8];
    float4 bq0 = ((const float4*)b)[q], bq1 = ((const float4*)b)[q + 8];
    a0.x = dd * a0.x + bq0.x; a0.y = dd * a0.y + bq0.y;
    a0.z = dd * a0.z + bq0.z; a0.w = dd * a0.w + bq0.w;
    a1.x = dd * a1.x + bq1.x; a1.y = dd * a1.y + bq1.y;
    a1.z = dd * a1.z + bq1.z; a1.w = dd * a1.w + bq1.w;
    float4 c0 = make_float4(0.f, 0.f, 0.f, 0.f);
    float4 c1 = make_float4(0.f, 0.f, 0.f, 0.f);
    int e = s0, end = s0 + deg;
    for (; e + 1 < end; e += 2) {
        int sa = g_csr[e], sb = g_csr[e + 1];
        float wa = g_wgt[e], wb = g_wgt[e + 1];
        const float4* pa = (const float4*)&g_hw[(long long)sa * HID];
        const float4* pb = (const float4*)&g_hw[(long long)sb * HID];
        float4 va0 = pa[q], va1 = pa[q + 8];
        float4 vb0 = pb[q], vb1 = pb[q + 8];
        a0.x += wa * va0.x; a0.y += wa * va0.y; a0.z += wa * va0.z; a0.w += wa * va0.w;
        a1.x += wa * va1.x; a1.y += wa * va1.y; a1.z += wa * va1.z; a1.w += wa * va1.w;
        c0.x += wb * vb0.x; c0.y += wb * vb0.y; c0.z += wb * vb0.z; c0.w += wb * vb0.w;
        c1.x += wb * vb1.x; c1.y += wb * vb1.y; c1.z += wb * vb1.z; c1.w += wb * vb1.w;
    }
    if (e < end) {
        int sa = g_csr[e];
        float wa = g_wgt[e];
        const float4* pa = (const float4*)&g_hw[(long long)sa * HID];
        float4 va0 = pa[q], va1 = pa[q + 8];
        a0.x += wa * va0.x; a0.y += wa * va0.y; a0.z += wa * va0.z; a0.w += wa * va0.w;
        a1.x += wa * va1.x; a1.y += wa * va1.y; a1.z += wa * va1.z; a1.w += wa * va1.w;
    }
    a0.x += c0.x; a0.y += c0.y; a0.z += c0.z; a0.w += c0.w;
    a1.x += c1.x; a1.y += c1.y; a1.z += c1.z; a1.w += c1.w;
    float4* ap = (float4*)&g_agg[(long long)n * HID];
    ap[q] = a0;
    ap[q + 8] = a1;
}

// ---- global mean pool: batch sorted ----
#define NPB 256
__global__ void k_pool(const int* __restrict__ batch) {
    int c = threadIdx.x;          // 0..63
    int n0 = blockIdx.x * NPB;
    int n1 = min(n0 + NPB, NN);
    int cur_g = batch[n0];
    float acc = 0.0f, cnt = 0.0f;
    for (int n = n0; n < n1; n++) {
        int g = batch[n];
        if (g != cur_g) {
            atomicAdd(&g_sums[cur_g * HID + c], acc);
            if (c == 0) atomicAdd(&g_gcnt[cur_g], cnt);
            acc = 0.0f; cnt = 0.0f; cur_g = g;
        }
        acc += g_agg[(long long)n * HID + c];
        cnt += 1.0f;
    }
    atomicAdd(&g_sums[cur_g * HID + c], acc);
    if (c == 0) atomicAdd(&g_gcnt[cur_g], cnt);
}

// ---- final linear ----
__global__ void k_fin(const float* __restrict__ lw,
                      const float* __restrict__ lb,
                      float* __restrict__ out) {
    int g = threadIdx.x;
    if (g >= NG) return;
    float inv = 1.0f / fmaxf(g_gcnt[g], 1.0f);
    float acc[OC];
#pragma unroll
    for (int o = 0; o < OC; o++) acc[o] = lb[o];
    for (int k = 0; k < HID; k++) {
        float v = g_sums[g * HID + k] * inv;
#pragma unroll
        for (int o = 0; o < OC; o++) acc[o] += v * lw[k * OC + o];
    }
#pragma unroll
    for (int o = 0; o < OC; o++) out[g * OC + o] = acc[o];
}

extern "C" void kernel_launch(void* const* d_in, const int* in_sizes, int n_in,
                              void* d_out, int out_size) {
    const float* x   = (const float*)d_in[0];
    const int* ei    = (const int*)d_in[1];
    const int* bat   = (const int*)d_in[2];
    const float* W0  = (const float*)d_in[3];
    const float* b0  = (const float*)d_in[4];
    const float* W1  = (const float*)d_in[5];
    const float* b1  = (const float*)d_in[6];
    const float* W2  = (const float*)d_in[7];
    const float* b2  = (const float*)d_in[8];
    const float* lw  = (const float*)d_in[9];
    const float* lb  = (const float*)d_in[10];
    float* out       = (float*)d_out;

    const int TB = 256;
    // CSR build
    k_zero<<<(NN + TB - 1) / TB, TB>>>();
    k_hist<<<(EE + TB - 1) / TB, TB>>>(ei);
    k_scan1<<<NB, 256>>>();
    k_scan2<<<1, 512>>>();
    k_scan3<<<(NN + TB - 1) / TB, TB>>>();
    k_fill<<<(EE + TB - 1) / TB, TB>>>(ei);

    int mm_grid = (NN + 15) / 16;
    int g32_grid = (NN + 31) / 32;

    // layer 0: aggregate x (7ch), then mm -> g_agg (+b0)
    k_gather7<<<g32_grid, TB>>>(x);
    k_mm7<<<mm_grid, TB>>>(W0, b0);

    // layer 1
    k_mm64<<<mm_grid, TB>>>(W1);
    k_gather64<<<g32_grid, TB>>>(b1);

    // layer 2
    k_mm64<<<mm_grid, TB>>>(W2);
    k_gather64<<<g32_grid, TB>>>(b2);

    // pool + linear
    k_pool<<<(NN + NPB - 1) / NPB, 64>>>(bat);
    k_fin<<<1, TB>>>(lw, lb, out);
}

// round 6
// speedup vs baseline: 2.1007x; 1.0683x over previous
#include <cuda_runtime.h>
#include <cuda_fp16.h>

#define NN 100000
#define EE 1200000
#define HID 64
#define NG 256
#define OC 10
#define IN0 7

// ---- scratch (static device globals) ----
__device__ int   g_cnti[NN];
__device__ int   g_rowp[NN];
__device__ int   g_cursor[NN];
__device__ int   g_total;
__device__ int   g_csr[EE];
__device__ float g_wgt[EE];
__device__ float g_dis[NN];
__device__ float g_aggx[NN * IN0];
__device__ __align__(256) __half g_hwh[NN * HID];   // fp16 hw rows (128B)
__device__ float g_agg[NN * HID];
__device__ float g_sums[NG * HID];
__device__ float g_gcnt[NG];

// ---- zero counters ----
__global__ void k_zero() {
    int i = blockIdx.x * blockDim.x + threadIdx.x;
    if (i < NN) g_cnti[i] = 0;
    if (i < NG * HID) g_sums[i] = 0.0f;
    if (i < NG) g_gcnt[i] = 0.0f;
    if (i == 0) g_total = 0;
}

// ---- histogram on dst ----
__global__ void k_hist(const int* __restrict__ ei) {
    int e = blockIdx.x * blockDim.x + threadIdx.x;
    if (e < EE) atomicAdd(&g_cnti[ei[EE + e]], 1);
}

// ---- fused scan: per-block local scan + atomic base claim ----
// CSR regions need not follow node order; any disjoint assignment works.
__global__ void k_scanA() {
    __shared__ int sm[256];
    __shared__ int base_sm;
    int t = threadIdx.x;
    int i = blockIdx.x * 256 + t;
    int v = (i < NN) ? g_cnti[i] : 0;
    sm[t] = v;
    __syncthreads();
#pragma unroll
    for (int off = 1; off < 256; off <<= 1) {
        int add = (t >= off) ? sm[t - off] : 0;
        __syncthreads();
        sm[t] += add;
        __syncthreads();
    }
    if (t == 255) base_sm = atomicAdd(&g_total, sm[255]);
    __syncthreads();
    if (i < NN) {
        int r = base_sm + sm[t] - v;   // exclusive within block + block base
        g_rowp[i] = r;
        g_cursor[i] = r;
        g_dis[i] = rsqrtf((float)v + 1.0f);
    }
}

// ---- fill CSR ----
__global__ void k_fill(const int* __restrict__ ei) {
    int e = blockIdx.x * blockDim.x + threadIdx.x;
    if (e >= EE) return;
    int src = ei[e];
    int dst = ei[EE + e];
    int pos = atomicAdd(&g_cursor[dst], 1);
    g_csr[pos] = src;
    g_wgt[pos] = g_dis[src] * g_dis[dst];
}

// ---- layer-0 gather in input space (7ch), 8 threads/node ----
__global__ void k_gather7(const float* __restrict__ x) {
    int t = threadIdx.x;
    int n = blockIdx.x * 32 + (t >> 3);
    int c = t & 7;
    if (n >= NN || c >= IN0) return;
    int s0 = g_rowp[n], deg = g_cnti[n];
    float d = g_dis[n];
    float acc0 = d * d * x[(long long)n * IN0 + c];
    float acc1 = 0.0f;
    int e = s0, end = s0 + deg;
    for (; e + 1 < end; e += 2) {
        int sa = g_csr[e], sb = g_csr[e + 1];
        float wa = g_wgt[e], wb = g_wgt[e + 1];
        acc0 += wa * x[(long long)sa * IN0 + c];
        acc1 += wb * x[(long long)sb * IN0 + c];
    }
    if (e < end) acc0 += g_wgt[e] * x[(long long)g_csr[e] * IN0 + c];
    g_aggx[(long long)n * IN0 + c] = acc0 + acc1;
}

// ---- dense mm7: agg = aggx @ W0 + b0 ----
__global__ void k_mm7(const float* __restrict__ W,
                      const float* __restrict__ b) {
    __shared__ float4 Ws[IN0 * 16];
    __shared__ float  hs[16 * IN0];
    __shared__ float4 bs[16];
    int t = threadIdx.x;
    if (t < IN0 * 16) Ws[t] = ((const float4*)W)[t];
    if (t < 16) bs[t] = ((const float4*)b)[t];
    int node0 = blockIdx.x * 16;
    for (int i = t; i < 16 * IN0; i += 256) {
        int nd = node0 + i / IN0;
        hs[i] = (nd < NN) ? g_aggx[(long long)nd * IN0 + (i % IN0)] : 0.0f;
    }
    __syncthreads();
    int node = node0 + (t >> 4);
    int q = t & 15;
    if (node < NN) {
        const float* hrow = &hs[(t >> 4) * IN0];
        float4 s = bs[q];
#pragma unroll
        for (int k = 0; k < IN0; k++) {
            float hv = hrow[k];
            float4 w = Ws[k * 16 + q];
            s.x += hv * w.x; s.y += hv * w.y; s.z += hv * w.z; s.w += hv * w.w;
        }
        ((float4*)&g_agg[(long long)node * HID])[q] = s;
    }
}

// ---- dense mm64: hwh = fp16( relu(agg) @ W ) ----
__global__ void k_mm64(const float* __restrict__ W) {
    __shared__ float4 Ws4[HID * 16];    // 16 KB
    __shared__ float4 hs4[16 * 16];     // 4 KB
    int t = threadIdx.x;
#pragma unroll
    for (int i = 0; i < 4; i++) Ws4[t + 256 * i] = ((const float4*)W)[t + 256 * i];
    int node0 = blockIdx.x * 16;
    int nl = t >> 4;
    int q = t & 15;
    int node = node0 + nl;
    {
        float4 v = make_float4(0.f, 0.f, 0.f, 0.f);
        if (node < NN) v = ((const float4*)&g_agg[(long long)node * HID])[q];
        v.x = fmaxf(v.x, 0.f); v.y = fmaxf(v.y, 0.f);
        v.z = fmaxf(v.z, 0.f); v.w = fmaxf(v.w, 0.f);
        hs4[nl * 16 + q] = v;
    }
    __syncthreads();
    if (node < NN) {
        const float* hrow = (const float*)&hs4[nl * 16];
        float4 s = make_float4(0.f, 0.f, 0.f, 0.f);
#pragma unroll
        for (int k = 0; k < HID; k++) {
            float hv = hrow[k];
            float4 w = Ws4[k * 16 + q];
            s.x += hv * w.x; s.y += hv * w.y; s.z += hv * w.z; s.w += hv * w.w;
        }
        __half2 h0 = __floats2half2_rn(s.x, s.y);
        __half2 h1 = __floats2half2_rn(s.z, s.w);
        uint2 o;
        o.x = *(unsigned int*)&h0;
        o.y = *(unsigned int*)&h1;
        ((uint2*)(g_hwh + (long long)node * HID))[q] = o;
    }
}

// ---- fp16 row unpack helper ----
__device__ __forceinline__ void unpack8(uint4 u, float* f) {
    const __half2* h = (const __half2*)&u;
#pragma unroll
    for (int j = 0; j < 4; j++) {
        float2 p = __half22float2(h[j]);
        f[2 * j] = p.x;
        f[2 * j + 1] = p.y;
    }
}

// ---- 64-ch gather over fp16 hw: 8 threads/node, 8 channels/thread ----
__global__ void k_gather64h(const float* __restrict__ b) {
    int t = threadIdx.x;
    int n = blockIdx.x * 32 + (t >> 3);
    int q = t & 7;                       // channels [8q, 8q+8)
    if (n >= NN) return;
    int s0 = g_rowp[n], deg = g_cnti[n];
    float d = g_dis[n];
    float dd = d * d;
    float acc[8], acc2[8], tmp[8];
    uint4 self = ((const uint4*)(g_hwh + (long long)n * HID))[q];
    unpack8(self, tmp);
    float4 b0 = ((const float4*)b)[q * 2];
    float4 b1 = ((const float4*)b)[q * 2 + 1];
    acc[0] = dd * tmp[0] + b0.x; acc[1] = dd * tmp[1] + b0.y;
    acc[2] = dd * tmp[2] + b0.z; acc[3] = dd * tmp[3] + b0.w;
    acc[4] = dd * tmp[4] + b1.x; acc[5] = dd * tmp[5] + b1.y;
    acc[6] = dd * tmp[6] + b1.z; acc[7] = dd * tmp[7] + b1.w;
#pragma unroll
    for (int i = 0; i < 8; i++) acc2[i] = 0.0f;
    int e = s0, end = s0 + deg;
    for (; e + 1 < end; e += 2) {
        int sa = g_csr[e], sb = g_csr[e + 1];
        float wa = g_wgt[e], wb = g_wgt[e + 1];
        uint4 va = ((const uint4*)(g_hwh + (long long)sa * HID))[q];
        uint4 vb = ((const uint4*)(g_hwh + (long long)sb * HID))[q];
        float fa[8], fb[8];
        unpack8(va, fa);
        unpack8(vb, fb);
#pragma unroll
        for (int i = 0; i < 8; i++) acc[i] += wa * fa[i];
#pragma unroll
        for (int i = 0; i < 8; i++) acc2[i] += wb * fb[i];
    }
    if (e < end) {
        int sa = g_csr[e];
        float wa = g_wgt[e];
        uint4 va = ((const uint4*)(g_hwh + (long long)sa * HID))[q];
        float fa[8];
        unpack8(va, fa);
#pragma unroll
        for (int i = 0; i < 8; i++) acc[i] += wa * fa[i];
    }
#pragma unroll
    for (int i = 0; i < 8; i++) acc[i] += acc2[i];
    float4* ap = (float4*)&g_agg[(long long)n * HID + q * 8];
    ap[0] = make_float4(acc[0], acc[1], acc[2], acc[3]);
    ap[1] = make_float4(acc[4], acc[5], acc[6], acc[7]);
}

// ---- global mean pool: batch sorted ----
#define NPB 256
__global__ void k_pool(const int* __restrict__ batch) {
    int c = threadIdx.x;          // 0..63
    int n0 = blockIdx.x * NPB;
    int n1 = min(n0 + NPB, NN);
    int cur_g = batch[n0];
    float acc = 0.0f, cnt = 0.0f;
    for (int n = n0; n < n1; n++) {
        int g = batch[n];
        if (g != cur_g) {
            atomicAdd(&g_sums[cur_g * HID + c], acc);
            if (c == 0) atomicAdd(&g_gcnt[cur_g], cnt);
            acc = 0.0f; cnt = 0.0f; cur_g = g;
        }
        acc += g_agg[(long long)n * HID + c];
        cnt += 1.0f;
    }
    atomicAdd(&g_sums[cur_g * HID + c], acc);
    if (c == 0) atomicAdd(&g_gcnt[cur_g], cnt);
}

// ---- final linear ----
__global__ void k_fin(const float* __restrict__ lw,
                      const float* __restrict__ lb,
                      float* __restrict__ out) {
    int g = threadIdx.x;
    if (g >= NG) return;
    float inv = 1.0f / fmaxf(g_gcnt[g], 1.0f);
    float acc[OC];
#pragma unroll
    for (int o = 0; o < OC; o++) acc[o] = lb[o];
    for (int k = 0; k < HID; k++) {
        float v = g_sums[g * HID + k] * inv;
#pragma unroll
        for (int o = 0; o < OC; o++) acc[o] += v * lw[k * OC + o];
    }
#pragma unroll
    for (int o = 0; o < OC; o++) out[g * OC + o] = acc[o];
}

extern "C" void kernel_launch(void* const* d_in, const int* in_sizes, int n_in,
                              void* d_out, int out_size) {
    const float* x   = (const float*)d_in[0];
    const int* ei    = (const int*)d_in[1];
    const int* bat   = (const int*)d_in[2];
    const float* W0  = (const float*)d_in[3];
    const float* b0  = (const float*)d_in[4];
    const float* W1  = (const float*)d_in[5];
    const float* b1  = (const float*)d_in[6];
    const float* W2  = (const float*)d_in[7];
    const float* b2  = (const float*)d_in[8];
    const float* lw  = (const float*)d_in[9];
    const float* lb  = (const float*)d_in[10];
    float* out       = (float*)d_out;

    const int TB = 256;
    // CSR build (4 launches)
    k_zero<<<(NN + TB - 1) / TB, TB>>>();
    k_hist<<<(EE + TB - 1) / TB, TB>>>(ei);
    k_scanA<<<(NN + 255) / 256, 256>>>();
    k_fill<<<(EE + TB - 1) / TB, TB>>>(ei);

    int mm_grid = (NN + 15) / 16;
    int g32_grid = (NN + 31) / 32;

    // layer 0: aggregate x (7ch), then mm -> g_agg (+b0)
    k_gather7<<<g32_grid, TB>>>(x);
    k_mm7<<<mm_grid, TB>>>(W0, b0);

    // layer 1
    k_mm64<<<mm_grid, TB>>>(W1);
    k_gather64h<<<g32_grid, TB>>>(b1);

    // layer 2
    k_mm64<<<mm_grid, TB>>>(W2);
    k_gather64h<<<g32_grid, TB>>>(b2);

    // pool + linear
    k_pool<<<(NN + NPB - 1) / NPB, 64>>>(bat);
    k_fin<<<1, TB>>>(lw, lb, out);
}